// round 15
// baseline (speedup 1.0000x reference)
#include <cuda_runtime.h>
#include <cstdint>

// Problem constants
#define A_BATCH 128
#define M_LEN   256
#define D_DIM   16
#define MM      255            // PDE grid size (M-1)
#define NTASK   384            // 3 PDE solves x 128 batch

// Ring geometry: one slot per column of raw g values (1 float per cell).
// Lane region = 12 words (8 data + 4 pad): quad stride 3 is coprime to 32
// -> conflict-free LDS.128/STS.128. SLOT_W % 32 == 0 -> slot-independent
// banks. RB=60 -> producer run-ahead = RB-31 = 29 columns (decoupling);
// gate: cons >= c-29. Consumer publish lag <=3 -> deadlock-free.
#define RB      60
#define SLOT_W  384            // 12 words * 32 lanes
#define SLOT_B  (SLOT_W * 4)   // 1536 bytes
#define RING_W  (RB * SLOT_W)  // 23040 words
#define DY_W    (MM * D_DIM)   // 4080 words
#define FLAGS_OFF (RING_W + DY_W)
#define TEAM_W  (FLAGS_OFF + 8)
#define SMEM_BYTES (TEAM_W * 4)   // 108,512 B -> 2 CTAs/SM co-resident

#define K12 0.0833333333333333f

typedef unsigned long long u64;
typedef unsigned int u32;

__device__ float g_partial[NTASK];
__device__ int   g_done = 0;       // last-CTA counter (reset by the last CTA)

__device__ __forceinline__ u64 pack2(float lo, float hi) {
    u64 r; asm("mov.b64 %0,{%1,%2};" : "=l"(r) : "f"(lo), "f"(hi)); return r;
}
__device__ __forceinline__ void unpack2(u64 v, float& lo, float& hi) {
    asm("mov.b64 {%0,%1},%2;" : "=f"(lo), "=f"(hi) : "l"(v));
}
__device__ __forceinline__ u64 fma2(u64 a, u64 b, u64 c) {
    u64 d; asm("fma.rn.f32x2 %0,%1,%2,%3;" : "=l"(d) : "l"(a), "l"(b), "l"(c)); return d;
}
__device__ __forceinline__ u64 mul2(u64 a, u64 b) {
    u64 d; asm("mul.rn.f32x2 %0,%1,%2;" : "=l"(d) : "l"(a), "l"(b)); return d;
}
__device__ __forceinline__ int lds_acq(u32 a) {
    int v; asm volatile("ld.acquire.cta.shared.b32 %0,[%1];" : "=r"(v) : "r"(a)); return v;
}
__device__ __forceinline__ void sts_rel(u32 a, int v) {
    asm volatile("st.release.cta.shared.b32 [%0],%1;" :: "r"(a), "r"(v));
}
__device__ __forceinline__ void lds128(u32 a, float& x, float& y, float& z, float& w) {
    asm volatile("ld.shared.v4.f32 {%0,%1,%2,%3},[%4];"
                 : "=f"(x), "=f"(y), "=f"(z), "=f"(w) : "r"(a));
}
__device__ __forceinline__ void sts128(u32 a, float x, float y, float z, float w) {
    asm volatile("st.shared.v4.f32 [%0],{%1,%2,%3,%4};"
                 :: "r"(a), "f"(x), "f"(y), "f"(z), "f"(w));
}

// One CTA = one task = 128 threads. Consumer warp ALTERNATES by placement
// round: co-resident CTAs on an SM are bid and bid+148 (classic-launch LUT
// keyed on bid%148), so qc = 3 - ((bid/148)&1) puts the two consumers on
// DIFFERENT SMSPs (3 and 2) -> each scheduler hosts consumer+producer
// (~164 cyc/step fma load) instead of consumer+consumer (~220). Producers
// (remaining 3 warps; warp p owns columns ≡ p mod 3) store raw g; consumer
// reconstructs (c1,c2) with the producer's exact FFMA sequence.
__global__ void __launch_bounds__(128, 2) sig_pde_kernel(
    const float* __restrict__ X, const float* __restrict__ Y,
    float* __restrict__ out)
{
    extern __shared__ float smem[];
    u32 sb;
    asm("{.reg .u64 t; cvta.to.shared.u64 t,%1; cvt.u32.u64 %0,t;}"
        : "=r"(sb) : "l"(smem));

    const int t    = threadIdx.x;
    const int q    = t >> 5;           // warp 0..3
    const int lane = t & 31;

    const int task = (int)blockIdx.x;
    const int pde  = task >> 7;        // 0:(X,X) 1:(Y,Y) 2:(X,Y)
    const int a    = task & 127;
    const float* rowsrc = (pde == 1 ? Y : X) + (size_t)a * (M_LEN * D_DIM);
    const float* colsrc = (pde == 0 ? X : Y) + (size_t)a * (M_LEN * D_DIM);

    float* s_dY = smem + RING_W;
    const u32 ring_b  = sb;
    const u32 flags_b = sb + FLAGS_OFF * 4;

    // dY[j][k] = colsrc[j+1][k] - colsrc[j][k]
    for (int idx = t; idx < DY_W; idx += 128)
        s_dY[idx] = colsrc[idx + D_DIM] - colsrc[idx];
    if (t < 4) ((volatile int*)(smem + FLAGS_OFF))[t] = -1; // done0..2, cons
    __syncthreads();   // the ONLY cta barrier

    // consumer warp: SMSP 3 for placement round 0, SMSP 2 for round 1
    const int qc = 3 - ((task / 148) & 1);

    if (q == qc) {
        // ======================= CONSUMER =======================
        float L[8];
#pragma unroll
        for (int r = 0; r < 8; r++) L[r] = 1.0f;     // K[row+1][0] = 1
        float nb_prev = 1.0f, last = 0.0f;
        u32 ad = ring_b + 48u * (u32)lane;
        const u32 ad_lim = ad + (u32)(RB * SLOT_B);
        const u32 cons_a = flags_b + 12;
        const u32 fa0 = flags_b, fa1 = flags_b + 4, fa2 = flags_b + 8;
        int f0 = -1, f1 = -1, f2 = -1;

        auto waitf = [&](int& f, u32 fa, int s) {
            if (f < s) { do { f = lds_acq(fa); } while (f < s); }
        };
        auto loadR = [&](float* G) {                 // load g col at ad, advance
            lds128(ad,      G[0], G[1], G[2], G[3]);
            lds128(ad + 16, G[4], G[5], G[6], G[7]);
            ad += SLOT_B;
            if (ad >= ad_lim) ad -= (u32)(RB * SLOT_B);
        };
        auto chain = [&](const float* G, float nb_new) {
            // reconstruct coefficients (producer's exact op sequence)
            float c1[8], c2[8];
#pragma unroll
            for (int r = 0; r < 8; r++) {
                const float g = G[r];
                const float h = g * g;
                const float u = fmaf(h,  K12, 1.0f);
                c1[r] = fmaf(g, 0.5f, u);
                c2[r] = fmaf(h, -K12, 1.0f);
            }
            const float up0 = (lane == 0) ? 1.0f : nb_new;
            const float dg0 = (lane == 0) ? 1.0f : nb_prev;
            float P0 = fmaf(L[0], c1[0], -(dg0  * c2[0]));
            float P1 = fmaf(L[1], c1[1], -(L[0] * c2[1]));
            float P2 = fmaf(L[2], c1[2], -(L[1] * c2[2]));
            float P3 = fmaf(L[3], c1[3], -(L[2] * c2[3]));
            float P4 = fmaf(L[4], c1[4], -(L[3] * c2[4]));
            float P5 = fmaf(L[5], c1[5], -(L[4] * c2[5]));
            float P6 = fmaf(L[6], c1[6], -(L[5] * c2[6]));
            float P7 = fmaf(L[7], c1[7], -(L[6] * c2[7]));
            float k = fmaf(up0, c1[0], P0); L[0] = k;
            k = fmaf(k, c1[1], P1); L[1] = k;
            k = fmaf(k, c1[2], P2); L[2] = k;
            k = fmaf(k, c1[3], P3); L[3] = k;
            k = fmaf(k, c1[4], P4); L[4] = k;
            k = fmaf(k, c1[5], P5); L[5] = k;
            k = fmaf(k, c1[6], P6); L[6] = k;
            k = fmaf(k, c1[7], P7); L[7] = k;
            last = k;
            nb_prev = nb_new;
        };
        auto body_ld = [&](float nb_new) {           // direct load + chain
            float G[8];
            loadR(G);
            chain(G, nb_new);
        };

        // ---- ramp: s = 0..32 (lane predicates + flag checks) ----
#pragma unroll 1
        for (int s = 0; s < 33; s += 3) {
            { float nb = __shfl_up_sync(0xffffffffu, last, 1);
              waitf(f0, fa0, s);     if (lane <= s)     body_ld(nb); }
            { float nb = __shfl_up_sync(0xffffffffu, last, 1);
              waitf(f1, fa1, s + 1); if (lane <= s + 1) body_ld(nb); }
            { float nb = __shfl_up_sync(0xffffffffu, last, 1);
              waitf(f2, fa2, s + 2); if (lane <= s + 2) body_ld(nb); }
            if (lane == 0) sts_rel(cons_a, s + 2);
        }

        // ---- steady (pipelined): steps 33..248 in 6-step groups ----
        float R[8], T[8];
        waitf(f0, fa0, 33);
        loadR(R);                                    // data for step 33
#pragma unroll 1
        for (int s = 33; s < 249; s += 6) {
            { float nb = __shfl_up_sync(0xffffffffu, last, 1);
              waitf(f1, fa1, s + 1); loadR(T); chain(R, nb); }
            { float nb = __shfl_up_sync(0xffffffffu, last, 1);
              waitf(f2, fa2, s + 2); loadR(R); chain(T, nb); }
            { float nb = __shfl_up_sync(0xffffffffu, last, 1);
              waitf(f0, fa0, s + 3); loadR(T); chain(R, nb); }
            if (lane == 0) sts_rel(cons_a, s + 2);
            { float nb = __shfl_up_sync(0xffffffffu, last, 1);
              waitf(f1, fa1, s + 4); loadR(R); chain(T, nb); }
            { float nb = __shfl_up_sync(0xffffffffu, last, 1);
              waitf(f2, fa2, s + 5); loadR(T); chain(R, nb); }
            { float nb = __shfl_up_sync(0xffffffffu, last, 1);
              waitf(f0, fa0, s + 6); loadR(R); chain(T, nb); }
            if (lane == 0) sts_rel(cons_a, s + 5);
        }
        // ---- peel: steps 249..254 (last wait clamped; junk preload ok) ----
        { float nb = __shfl_up_sync(0xffffffffu, last, 1);
          waitf(f1, fa1, 250); loadR(T); chain(R, nb); }       // 249
        { float nb = __shfl_up_sync(0xffffffffu, last, 1);
          waitf(f2, fa2, 251); loadR(R); chain(T, nb); }       // 250
        { float nb = __shfl_up_sync(0xffffffffu, last, 1);
          waitf(f0, fa0, 252); loadR(T); chain(R, nb); }       // 251
        if (lane == 0) sts_rel(cons_a, 251);
        { float nb = __shfl_up_sync(0xffffffffu, last, 1);
          waitf(f1, fa1, 253); loadR(R); chain(T, nb); }       // 252
        { float nb = __shfl_up_sync(0xffffffffu, last, 1);
          waitf(f2, fa2, 254); loadR(T); chain(R, nb); }       // 253
        { float nb = __shfl_up_sync(0xffffffffu, last, 1);
          loadR(R); chain(T, nb); }                            // 254 (junk preload)
        if (lane == 0) sts_rel(cons_a, 254);
        // rewind the junk preload so tail's direct loads hit the right column
        ad += (u32)(RB * SLOT_B) - SLOT_B;
        if (ad >= ad_lim) ad -= (u32)(RB * SLOT_B);

        // ---- tail: s = 255..285, flag-free (all cols <=254 already waited) --
#pragma unroll 1
        for (int s = 255; s < 286; s++) {
            float nb = __shfl_up_sync(0xffffffffu, last, 1);
            if (lane >= s - 254) body_ld(nb);
        }
        // K[255][255] = L[6] of lane 31 (global row 254)
        if (lane == 31) g_partial[task] = L[6];

        // ---- fused reduction: last CTA sums all partials ----
        int old = 0;
        if (lane == 31) {
            __threadfence();                         // g_partial visible
            old = atomicAdd(&g_done, 1);
        }
        old = __shfl_sync(0xffffffffu, old, 31);
        if (old == NTASK - 1) {
            __threadfence();                         // see all g_partial
            float v = 0.0f;
#pragma unroll
            for (int i = lane; i < NTASK; i += 32) {
                const float w = (i >= 256) ? -2.0f : 1.0f;
                v += w * g_partial[i];
            }
#pragma unroll
            for (int off = 16; off > 0; off >>= 1)
                v += __shfl_down_sync(0xffffffffu, v, off);
            if (lane == 0) {
                g_done = 0;                          // reset for next replay
                out[0] = v * (1.0f / (float)A_BATCH);
            }
        }
    } else {
        // ======================= PRODUCER (3 warps) =======================
        const int p = q - (q > qc ? 1 : 0);          // stream 0..2

        // dX for rows 8*lane .. 8*lane+7 in registers (f32x2 packed)
        u64 dxp[8][8];
#pragma unroll
        for (int r = 0; r < 8; r++) {
            const int i = 8 * lane + r;
            if (i < MM) {
                const float4* pa = reinterpret_cast<const float4*>(rowsrc + i * D_DIM);
                const float4* pb = reinterpret_cast<const float4*>(rowsrc + (i + 1) * D_DIM);
#pragma unroll
                for (int k = 0; k < 4; k++) {
                    float4 va = pa[k], vb = pb[k];
                    dxp[r][2 * k]     = pack2(vb.x - va.x, vb.y - va.y);
                    dxp[r][2 * k + 1] = pack2(vb.z - va.z, vb.w - va.w);
                }
            } else {                                  // row 255 -> g = 0
#pragma unroll
                for (int k = 0; k < 8; k++) dxp[r][k] = 0ull;
            }
        }

        int cons_c = -1;
        const u32 cons_a = flags_b + 12;
        const u32 done_a = flags_b + 4u * (u32)p;
        u32 colb = ring_b + (u32)p * SLOT_B + 48u * (u32)lane;
        const u32 colb_lim = ring_b + (u32)(RB * SLOT_B) + 48u * (u32)lane;
        const ulonglong2* dyp =
            reinterpret_cast<const ulonglong2*>(s_dY + p * D_DIM);

        auto produce = [&](ulonglong2 y0, ulonglong2 y1,
                           ulonglong2 y2, ulonglong2 y3) {
            float gv[8];
#pragma unroll
            for (int h = 0; h < 4; h++) {             // row pairs (2h, 2h+1)
                u64 acc_a = mul2(dxp[2 * h][0], y0.x);
                acc_a = fma2(dxp[2 * h][1], y0.y, acc_a);
                acc_a = fma2(dxp[2 * h][2], y1.x, acc_a);
                acc_a = fma2(dxp[2 * h][3], y1.y, acc_a);
                acc_a = fma2(dxp[2 * h][4], y2.x, acc_a);
                acc_a = fma2(dxp[2 * h][5], y2.y, acc_a);
                acc_a = fma2(dxp[2 * h][6], y3.x, acc_a);
                acc_a = fma2(dxp[2 * h][7], y3.y, acc_a);
                u64 acc_b = mul2(dxp[2 * h + 1][0], y0.x);
                acc_b = fma2(dxp[2 * h + 1][1], y0.y, acc_b);
                acc_b = fma2(dxp[2 * h + 1][2], y1.x, acc_b);
                acc_b = fma2(dxp[2 * h + 1][3], y1.y, acc_b);
                acc_b = fma2(dxp[2 * h + 1][4], y2.x, acc_b);
                acc_b = fma2(dxp[2 * h + 1][5], y2.y, acc_b);
                acc_b = fma2(dxp[2 * h + 1][6], y3.x, acc_b);
                acc_b = fma2(dxp[2 * h + 1][7], y3.y, acc_b);
                float lo_a, hi_a, lo_b, hi_b;
                unpack2(acc_a, lo_a, hi_a);
                unpack2(acc_b, lo_b, hi_b);
                gv[2 * h]     = lo_a + hi_a;
                gv[2 * h + 1] = lo_b + hi_b;
            }
            sts128(colb,      gv[0], gv[1], gv[2], gv[3]);
            sts128(colb + 16, gv[4], gv[5], gv[6], gv[7]);
            dyp += 3 * 4;                             // advance 3 columns
            colb += 3 * SLOT_B;
            if (colb >= colb_lim) colb -= (u32)(RB * SLOT_B);
        };

        int c = p;
#pragma unroll 1
        for (; c < RB; c += 3) {                      // no ring wait needed
            produce(dyp[0], dyp[1], dyp[2], dyp[3]);
            if (lane == 0) sts_rel(done_a, c);
        }
#pragma unroll 1
        for (; c < MM; c += 3) {                      // slot reuse: wait c-29
            // prefetch dY column before the spin (no ring dependence)
            const ulonglong2 y0 = dyp[0], y1 = dyp[1], y2 = dyp[2], y3 = dyp[3];
            const int need = c - (RB - 31);           // = c - 29
            while (cons_c < need) cons_c = lds_acq(cons_a);   // bare spin
            produce(y0, y1, y2, y3);
            if (lane == 0) sts_rel(done_a, c);
        }
    }
}

extern "C" void kernel_launch(void* const* d_in, const int* in_sizes, int n_in,
                              void* d_out, int out_size)
{
    const float* X = (const float*)d_in[0];
    const float* Y = (const float*)d_in[1];
    float* out = (float*)d_out;

    cudaFuncSetAttribute(sig_pde_kernel,
                         cudaFuncAttributeMaxDynamicSharedMemorySize, SMEM_BYTES);

    sig_pde_kernel<<<NTASK, 128, SMEM_BYTES>>>(X, Y, out);
}

// round 16
// speedup vs baseline: 1.0941x; 1.0941x over previous
#include <cuda_runtime.h>
#include <cstdint>

// Problem constants
#define A_BATCH 128
#define M_LEN   256
#define D_DIM   16
#define MM      255            // PDE grid size (M-1)
#define NTASK   384            // 3 PDE solves x 128 batch

// Ring geometry: one slot per column of raw g values (1 float per cell).
// Lane region = 12 words (8 data + 4 pad): quad stride 3 is coprime to 32
// -> conflict-free LDS.128/STS.128. SLOT_W % 32 == 0 -> slot-independent
// banks. RB=60 -> producer run-ahead = RB-31 = 29 columns (decoupling);
// gate: cons >= c-29. Consumer publish lag <=3 -> deadlock-free.
#define RB      60
#define SLOT_W  384            // 12 words * 32 lanes
#define SLOT_B  (SLOT_W * 4)   // 1536 bytes
#define RING_W  (RB * SLOT_W)  // 23040 words
#define DY_W    (MM * D_DIM)   // 4080 words
#define FLAGS_OFF (RING_W + DY_W)
#define TEAM_W  (FLAGS_OFF + 8)
#define SMEM_BYTES (TEAM_W * 4)   // 108,512 B -> 2 CTAs/SM co-resident

#define K12 0.0833333333333333f

typedef unsigned long long u64;
typedef unsigned int u32;

__device__ float g_partial[NTASK];
__device__ int   g_done = 0;       // last-CTA counter (reset by the last CTA)

__device__ __forceinline__ u64 pack2(float lo, float hi) {
    u64 r; asm("mov.b64 %0,{%1,%2};" : "=l"(r) : "f"(lo), "f"(hi)); return r;
}
__device__ __forceinline__ void unpack2(u64 v, float& lo, float& hi) {
    asm("mov.b64 {%0,%1},%2;" : "=f"(lo), "=f"(hi) : "l"(v));
}
__device__ __forceinline__ u64 fma2(u64 a, u64 b, u64 c) {
    u64 d; asm("fma.rn.f32x2 %0,%1,%2,%3;" : "=l"(d) : "l"(a), "l"(b), "l"(c)); return d;
}
__device__ __forceinline__ u64 mul2(u64 a, u64 b) {
    u64 d; asm("mul.rn.f32x2 %0,%1,%2;" : "=l"(d) : "l"(a), "l"(b)); return d;
}
__device__ __forceinline__ int lds_acq(u32 a) {
    int v; asm volatile("ld.acquire.cta.shared.b32 %0,[%1];" : "=r"(v) : "r"(a)); return v;
}
__device__ __forceinline__ void sts_rel(u32 a, int v) {
    asm volatile("st.release.cta.shared.b32 [%0],%1;" :: "r"(a), "r"(v));
}
__device__ __forceinline__ void lds_v2u64(u32 a, u64& x, u64& y) {
    asm volatile("ld.shared.v2.u64 {%0,%1},[%2];" : "=l"(x), "=l"(y) : "r"(a));
}
__device__ __forceinline__ void sts128(u32 a, float x, float y, float z, float w) {
    asm volatile("st.shared.v4.f32 [%0],{%1,%2,%3,%4};"
                 :: "r"(a), "f"(x), "f"(y), "f"(z), "f"(w));
}

// One CTA = one task = 128 threads. Consumer = warp 3; producers = warps
// 0..2 (warp p owns columns ≡ p mod 3; lane computes rows 8l..8l+7 from
// register dX and stores raw g). Consumer reconstructs (c1, -c2) from g in
// PACKED f32x2 (bitwise-identical rounding to the scalar form; the packed
// math halves the consumer's fma-pipe issue count per step). R14 protocol
// byte-for-byte: per-step cached waits, lane-0 publishes, RB=60 decoupling.
__global__ void __launch_bounds__(128, 2) sig_pde_kernel(
    const float* __restrict__ X, const float* __restrict__ Y,
    float* __restrict__ out)
{
    extern __shared__ float smem[];
    u32 sb;
    asm("{.reg .u64 t; cvta.to.shared.u64 t,%1; cvt.u32.u64 %0,t;}"
        : "=r"(sb) : "l"(smem));

    const int t    = threadIdx.x;
    const int q    = t >> 5;           // warp 0..3
    const int lane = t & 31;

    const int task = (int)blockIdx.x;
    const int pde  = task >> 7;        // 0:(X,X) 1:(Y,Y) 2:(X,Y)
    const int a    = task & 127;
    const float* rowsrc = (pde == 1 ? Y : X) + (size_t)a * (M_LEN * D_DIM);
    const float* colsrc = (pde == 0 ? X : Y) + (size_t)a * (M_LEN * D_DIM);

    float* s_dY = smem + RING_W;
    const u32 ring_b  = sb;
    const u32 flags_b = sb + FLAGS_OFF * 4;

    // dY[j][k] = colsrc[j+1][k] - colsrc[j][k]
    for (int idx = t; idx < DY_W; idx += 128)
        s_dY[idx] = colsrc[idx + D_DIM] - colsrc[idx];
    if (t < 4) ((volatile int*)(smem + FLAGS_OFF))[t] = -1; // done0..2, cons
    __syncthreads();   // the ONLY cta barrier

    if (q == 3) {
        // ======================= CONSUMER (warp 3) =======================
        const u64 ONE2  = pack2( 1.0f,  1.0f);
        const u64 MONE2 = pack2(-1.0f, -1.0f);
        const u64 HALF2 = pack2( 0.5f,  0.5f);
        const u64 K112  = pack2( K12,   K12);

        float L[8];
#pragma unroll
        for (int r = 0; r < 8; r++) L[r] = 1.0f;     // K[row+1][0] = 1
        float nb_prev = 1.0f, last = 0.0f;
        u32 ad = ring_b + 48u * (u32)lane;
        const u32 ad_lim = ad + (u32)(RB * SLOT_B);
        const u32 cons_a = flags_b + 12;
        const u32 fa0 = flags_b, fa1 = flags_b + 4, fa2 = flags_b + 8;
        int f0 = -1, f1 = -1, f2 = -1;

        auto waitf = [&](int& f, u32 fa, int s) {
            if (f < s) { do { f = lds_acq(fa); } while (f < s); }
        };
        auto loadR = [&](u64* G) {                   // g col as 4 f32x2 pairs
            lds_v2u64(ad,      G[0], G[1]);
            lds_v2u64(ad + 16, G[2], G[3]);
            ad += SLOT_B;
            if (ad >= ad_lim) ad -= (u32)(RB * SLOT_B);
        };
        auto chain = [&](const u64* G, float nb_new) {
            // packed reconstruction: c1 = 1 + g/2 + gg, c2n = -(1 - gg)
            const u64 h0 = mul2(G[0], G[0]);
            const u64 h1 = mul2(G[1], G[1]);
            const u64 h2 = mul2(G[2], G[2]);
            const u64 h3 = mul2(G[3], G[3]);
            const u64 u0 = fma2(h0, K112, ONE2);
            const u64 u1 = fma2(h1, K112, ONE2);
            const u64 u2 = fma2(h2, K112, ONE2);
            const u64 u3 = fma2(h3, K112, ONE2);
            const u64 c1p0 = fma2(G[0], HALF2, u0);
            const u64 c1p1 = fma2(G[1], HALF2, u1);
            const u64 c1p2 = fma2(G[2], HALF2, u2);
            const u64 c1p3 = fma2(G[3], HALF2, u3);
            const u64 n0 = fma2(h0, K112, MONE2);    // -(c2)
            const u64 n1 = fma2(h1, K112, MONE2);
            const u64 n2 = fma2(h2, K112, MONE2);
            const u64 n3 = fma2(h3, K112, MONE2);

            const float up0 = (lane == 0) ? 1.0f : nb_new;
            const float dg0 = (lane == 0) ? 1.0f : nb_prev;

            // packed partials: P = L*c1 + prev*(-c2)
            const u64 la0 = pack2(L[0], L[1]);
            const u64 la1 = pack2(L[2], L[3]);
            const u64 la2 = pack2(L[4], L[5]);
            const u64 la3 = pack2(L[6], L[7]);
            const u64 pv0 = pack2(dg0,  L[0]);
            const u64 pv1 = pack2(L[1], L[2]);
            const u64 pv2 = pack2(L[3], L[4]);
            const u64 pv3 = pack2(L[5], L[6]);
            const u64 Pp0 = fma2(la0, c1p0, mul2(pv0, n0));
            const u64 Pp1 = fma2(la1, c1p1, mul2(pv1, n1));
            const u64 Pp2 = fma2(la2, c1p2, mul2(pv2, n2));
            const u64 Pp3 = fma2(la3, c1p3, mul2(pv3, n3));

            float c10,c11,c12,c13,c14,c15,c16,c17;
            unpack2(c1p0, c10, c11); unpack2(c1p1, c12, c13);
            unpack2(c1p2, c14, c15); unpack2(c1p3, c16, c17);
            float P0,P1,P2,P3,P4,P5,P6,P7;
            unpack2(Pp0, P0, P1); unpack2(Pp1, P2, P3);
            unpack2(Pp2, P4, P5); unpack2(Pp3, P6, P7);

            // dependent chain (8 scalar FFMA)
            float k = fmaf(up0, c10, P0); L[0] = k;
            k = fmaf(k, c11, P1); L[1] = k;
            k = fmaf(k, c12, P2); L[2] = k;
            k = fmaf(k, c13, P3); L[3] = k;
            k = fmaf(k, c14, P4); L[4] = k;
            k = fmaf(k, c15, P5); L[5] = k;
            k = fmaf(k, c16, P6); L[6] = k;
            k = fmaf(k, c17, P7); L[7] = k;
            last = k;
            nb_prev = nb_new;
        };
        auto body_ld = [&](float nb_new) {           // direct load + chain
            u64 G[4];
            loadR(G);
            chain(G, nb_new);
        };

        // ---- ramp: s = 0..32 (lane predicates + flag checks) ----
#pragma unroll 1
        for (int s = 0; s < 33; s += 3) {
            { float nb = __shfl_up_sync(0xffffffffu, last, 1);
              waitf(f0, fa0, s);     if (lane <= s)     body_ld(nb); }
            { float nb = __shfl_up_sync(0xffffffffu, last, 1);
              waitf(f1, fa1, s + 1); if (lane <= s + 1) body_ld(nb); }
            { float nb = __shfl_up_sync(0xffffffffu, last, 1);
              waitf(f2, fa2, s + 2); if (lane <= s + 2) body_ld(nb); }
            if (lane == 0) sts_rel(cons_a, s + 2);
        }

        // ---- steady (pipelined): steps 33..248 in 6-step groups ----
        u64 R[4], T[4];
        waitf(f0, fa0, 33);
        loadR(R);                                    // data for step 33
#pragma unroll 1
        for (int s = 33; s < 249; s += 6) {
            { float nb = __shfl_up_sync(0xffffffffu, last, 1);
              waitf(f1, fa1, s + 1); loadR(T); chain(R, nb); }
            { float nb = __shfl_up_sync(0xffffffffu, last, 1);
              waitf(f2, fa2, s + 2); loadR(R); chain(T, nb); }
            { float nb = __shfl_up_sync(0xffffffffu, last, 1);
              waitf(f0, fa0, s + 3); loadR(T); chain(R, nb); }
            if (lane == 0) sts_rel(cons_a, s + 2);
            { float nb = __shfl_up_sync(0xffffffffu, last, 1);
              waitf(f1, fa1, s + 4); loadR(R); chain(T, nb); }
            { float nb = __shfl_up_sync(0xffffffffu, last, 1);
              waitf(f2, fa2, s + 5); loadR(T); chain(R, nb); }
            { float nb = __shfl_up_sync(0xffffffffu, last, 1);
              waitf(f0, fa0, s + 6); loadR(R); chain(T, nb); }
            if (lane == 0) sts_rel(cons_a, s + 5);
        }
        // ---- peel: steps 249..254 (last wait clamped; junk preload ok) ----
        { float nb = __shfl_up_sync(0xffffffffu, last, 1);
          waitf(f1, fa1, 250); loadR(T); chain(R, nb); }       // 249
        { float nb = __shfl_up_sync(0xffffffffu, last, 1);
          waitf(f2, fa2, 251); loadR(R); chain(T, nb); }       // 250
        { float nb = __shfl_up_sync(0xffffffffu, last, 1);
          waitf(f0, fa0, 252); loadR(T); chain(R, nb); }       // 251
        if (lane == 0) sts_rel(cons_a, 251);
        { float nb = __shfl_up_sync(0xffffffffu, last, 1);
          waitf(f1, fa1, 253); loadR(R); chain(T, nb); }       // 252
        { float nb = __shfl_up_sync(0xffffffffu, last, 1);
          waitf(f2, fa2, 254); loadR(T); chain(R, nb); }       // 253
        { float nb = __shfl_up_sync(0xffffffffu, last, 1);
          loadR(R); chain(T, nb); }                            // 254 (junk preload)
        if (lane == 0) sts_rel(cons_a, 254);
        // rewind the junk preload so tail's direct loads hit the right column
        ad += (u32)(RB * SLOT_B) - SLOT_B;
        if (ad >= ad_lim) ad -= (u32)(RB * SLOT_B);

        // ---- tail: s = 255..285, flag-free (all cols <=254 already waited) --
#pragma unroll 1
        for (int s = 255; s < 286; s++) {
            float nb = __shfl_up_sync(0xffffffffu, last, 1);
            if (lane >= s - 254) body_ld(nb);
        }
        // K[255][255] = L[6] of lane 31 (global row 254)
        if (lane == 31) g_partial[task] = L[6];

        // ---- fused reduction: last CTA sums all partials ----
        int old = 0;
        if (lane == 31) {
            __threadfence();                         // g_partial visible
            old = atomicAdd(&g_done, 1);
        }
        old = __shfl_sync(0xffffffffu, old, 31);
        if (old == NTASK - 1) {
            __threadfence();                         // see all g_partial
            float v = 0.0f;
#pragma unroll
            for (int i = lane; i < NTASK; i += 32) {
                const float w = (i >= 256) ? -2.0f : 1.0f;
                v += w * g_partial[i];
            }
#pragma unroll
            for (int off = 16; off > 0; off >>= 1)
                v += __shfl_down_sync(0xffffffffu, v, off);
            if (lane == 0) {
                g_done = 0;                          // reset for next replay
                out[0] = v * (1.0f / (float)A_BATCH);
            }
        }
    } else {
        // ======================= PRODUCER (warps 0..2) =======================
        const int p = q;                             // stream 0..2

        // dX for rows 8*lane .. 8*lane+7 in registers (f32x2 packed)
        u64 dxp[8][8];
#pragma unroll
        for (int r = 0; r < 8; r++) {
            const int i = 8 * lane + r;
            if (i < MM) {
                const float4* pa = reinterpret_cast<const float4*>(rowsrc + i * D_DIM);
                const float4* pb = reinterpret_cast<const float4*>(rowsrc + (i + 1) * D_DIM);
#pragma unroll
                for (int k = 0; k < 4; k++) {
                    float4 va = pa[k], vb = pb[k];
                    dxp[r][2 * k]     = pack2(vb.x - va.x, vb.y - va.y);
                    dxp[r][2 * k + 1] = pack2(vb.z - va.z, vb.w - va.w);
                }
            } else {                                  // row 255 -> g = 0
#pragma unroll
                for (int k = 0; k < 8; k++) dxp[r][k] = 0ull;
            }
        }

        int cons_c = -1;
        const u32 cons_a = flags_b + 12;
        const u32 done_a = flags_b + 4u * (u32)p;
        u32 colb = ring_b + (u32)p * SLOT_B + 48u * (u32)lane;
        const u32 colb_lim = ring_b + (u32)(RB * SLOT_B) + 48u * (u32)lane;
        const ulonglong2* dyp =
            reinterpret_cast<const ulonglong2*>(s_dY + p * D_DIM);

        auto produce = [&](ulonglong2 y0, ulonglong2 y1,
                           ulonglong2 y2, ulonglong2 y3) {
            float gv[8];
#pragma unroll
            for (int h = 0; h < 4; h++) {             // row pairs (2h, 2h+1)
                u64 acc_a = mul2(dxp[2 * h][0], y0.x);
                acc_a = fma2(dxp[2 * h][1], y0.y, acc_a);
                acc_a = fma2(dxp[2 * h][2], y1.x, acc_a);
                acc_a = fma2(dxp[2 * h][3], y1.y, acc_a);
                acc_a = fma2(dxp[2 * h][4], y2.x, acc_a);
                acc_a = fma2(dxp[2 * h][5], y2.y, acc_a);
                acc_a = fma2(dxp[2 * h][6], y3.x, acc_a);
                acc_a = fma2(dxp[2 * h][7], y3.y, acc_a);
                u64 acc_b = mul2(dxp[2 * h + 1][0], y0.x);
                acc_b = fma2(dxp[2 * h + 1][1], y0.y, acc_b);
                acc_b = fma2(dxp[2 * h + 1][2], y1.x, acc_b);
                acc_b = fma2(dxp[2 * h + 1][3], y1.y, acc_b);
                acc_b = fma2(dxp[2 * h + 1][4], y2.x, acc_b);
                acc_b = fma2(dxp[2 * h + 1][5], y2.y, acc_b);
                acc_b = fma2(dxp[2 * h + 1][6], y3.x, acc_b);
                acc_b = fma2(dxp[2 * h + 1][7], y3.y, acc_b);
                float lo_a, hi_a, lo_b, hi_b;
                unpack2(acc_a, lo_a, hi_a);
                unpack2(acc_b, lo_b, hi_b);
                gv[2 * h]     = lo_a + hi_a;
                gv[2 * h + 1] = lo_b + hi_b;
            }
            sts128(colb,      gv[0], gv[1], gv[2], gv[3]);
            sts128(colb + 16, gv[4], gv[5], gv[6], gv[7]);
            dyp += 3 * 4;                             // advance 3 columns
            colb += 3 * SLOT_B;
            if (colb >= colb_lim) colb -= (u32)(RB * SLOT_B);
        };

        int c = p;
#pragma unroll 1
        for (; c < RB; c += 3) {                      // no ring wait needed
            produce(dyp[0], dyp[1], dyp[2], dyp[3]);
            if (lane == 0) sts_rel(done_a, c);
        }
#pragma unroll 1
        for (; c < MM; c += 3) {                      // slot reuse: wait c-29
            // prefetch dY column before the spin (no ring dependence)
            const ulonglong2 y0 = dyp[0], y1 = dyp[1], y2 = dyp[2], y3 = dyp[3];
            const int need = c - (RB - 31);           // = c - 29
            while (cons_c < need) cons_c = lds_acq(cons_a);   // bare spin
            produce(y0, y1, y2, y3);
            if (lane == 0) sts_rel(done_a, c);
        }
    }
}

extern "C" void kernel_launch(void* const* d_in, const int* in_sizes, int n_in,
                              void* d_out, int out_size)
{
    const float* X = (const float*)d_in[0];
    const float* Y = (const float*)d_in[1];
    float* out = (float*)d_out;

    cudaFuncSetAttribute(sig_pde_kernel,
                         cudaFuncAttributeMaxDynamicSharedMemorySize, SMEM_BYTES);

    sig_pde_kernel<<<NTASK, 128, SMEM_BYTES>>>(X, Y, out);
}